// round 5
// baseline (speedup 1.0000x reference)
#include <cuda_runtime.h>
#include <cuda_bf16.h>

#define FULLMASK 0xffffffffu

// ---------------------------------------------------------------------------
// Analytic reduction (validated R1-R4, rel_err ~1e-5..2e-5):
// Measured observable is Z on wire 10, touched only by its vertex init and
// edge-loop iteration i=1; everything later commutes and drops out.
//   psi0      = U |vE0>|vN0>|0>|0>           (16-dim, iteration-0 gates)
//   phi_en    = sum_a psi0[en*4+a] * W_a,  W_a = U(|vE1>|vN1>|a>)
//   answer    = sum_en sum_s (+-) |phi_en[s]|^2     (sign: bit2 of s)
// 5 independent 16-dim evolutions run concurrently on lanes 0..4.
//
// R5: __launch_bounds__(32,1) -> register cap 255. R4 compiled to 48 regs
// and spilled all 10 gate matrices + state to local memory (LDL chains were
// the real bottleneck). Keeping everything register-resident removes them.
// ---------------------------------------------------------------------------

struct C2 { float x, y; };
__device__ __forceinline__ C2 cmul(C2 a, C2 b){
    return { a.x*b.x - a.y*b.y, a.x*b.y + a.y*b.x };
}
__device__ __forceinline__ C2 cmadd(C2 a, C2 b, C2 acc){ // acc + a*b
    return { fmaf(a.x, b.x, fmaf(-a.y, b.y, acc.x)),
             fmaf(a.x, b.y, fmaf( a.y, b.x, acc.y)) };
}

struct M2 { C2 m00, m01, m10, m11; };

__device__ __forceinline__ M2 mmul(const M2& A, const M2& B){
    M2 R;
    R.m00 = cmadd(A.m01, B.m10, cmul(A.m00, B.m00));
    R.m01 = cmadd(A.m01, B.m11, cmul(A.m00, B.m01));
    R.m10 = cmadd(A.m11, B.m10, cmul(A.m10, B.m00));
    R.m11 = cmadd(A.m11, B.m11, cmul(A.m10, B.m01));
    return R;
}

__device__ __forceinline__ M2 m_rx(float t){
    float c, s; __sincosf(0.5f*t, &s, &c);
    return { {c,0.f}, {0.f,-s}, {0.f,-s}, {c,0.f} };
}
__device__ __forceinline__ M2 m_ry(float t){
    float c, s; __sincosf(0.5f*t, &s, &c);
    return { {c,0.f}, {-s,0.f}, {s,0.f}, {c,0.f} };
}
__device__ __forceinline__ M2 m_rz(float t){
    float c, s; __sincosf(0.5f*t, &s, &c);
    return { {c,-s}, {0.f,0.f}, {0.f,0.f}, {c,s} };
}
// Fused Rx(t2)*Ry(t1)*Rz(t0)  (reference applies Rz, then Ry, then Rx)
__device__ __forceinline__ M2 m_fused(float t0, float t1, float t2){
    return mmul(m_rx(t2), mmul(m_ry(t1), m_rz(t0)));
}

template<int P>
__device__ __forceinline__ void apply1(C2* a, const M2& U){
#pragma unroll
    for (int s0 = 0; s0 < 16; s0++){
        if (s0 & (1 << P)) continue;
        const int s1 = s0 | (1 << P);
        C2 a0 = a[s0], a1 = a[s1];
        a[s0] = cmadd(U.m01, a1, cmul(U.m00, a0));
        a[s1] = cmadd(U.m11, a1, cmul(U.m10, a0));
    }
}
template<int PC, int PT>
__device__ __forceinline__ void applyc(C2* a, const M2& U){
#pragma unroll
    for (int s0 = 0; s0 < 16; s0++){
        if (!(s0 & (1 << PC)) || (s0 & (1 << PT))) continue;
        const int s1 = s0 | (1 << PT);
        C2 a0 = a[s0], a1 = a[s1];
        a[s0] = cmadd(U.m01, a1, cmul(U.m00, a0));
        a[s1] = cmadd(U.m11, a1, cmul(U.m10, a0));
    }
}
template<int PC, int PT>
__device__ __forceinline__ void cnotg(C2* a){
#pragma unroll
    for (int s0 = 0; s0 < 16; s0++){
        if (!(s0 & (1 << PC)) || (s0 & (1 << PT))) continue;
        const int s1 = s0 | (1 << PT);
        C2 t = a[s0]; a[s0] = a[s1]; a[s1] = t;
    }
}

struct Gates {
    M2 ci0, ci1, ci2, ci3;     // controlled init rotations
    M2 A0, A1, A2;             // fused strong0 (wires 3,2,1)
    M2 B0, B1, B2;             // fused strong1 (wires 1,2,0)
};

__device__ __forceinline__ void evolve(C2* a, const Gates& G){
    applyc<2,1>(a, G.ci0);     // ctrl(Rx): Nb -> A1
    applyc<3,1>(a, G.ci1);     // ctrl(Ry): E  -> A1
    applyc<2,0>(a, G.ci2);     // ctrl(Rz): Nb -> A2
    applyc<3,0>(a, G.ci3);     // ctrl(Ry): E  -> A2
    apply1<3>(a, G.A0);
    apply1<2>(a, G.A1);
    apply1<1>(a, G.A2);
    cnotg<3,2>(a); cnotg<2,1>(a); cnotg<1,3>(a);
    apply1<1>(a, G.B0);
    apply1<2>(a, G.B1);
    apply1<0>(a, G.B2);
    cnotg<1,2>(a); cnotg<2,0>(a); cnotg<0,1>(a);
}

__global__ void __launch_bounds__(32, 1)
QMessagePassing_44272522887312_kernel(
    const float* __restrict__ inp,     // inputs_flat [34]
    const float* __restrict__ inits,   // [4]
    const float* __restrict__ sp0,     // strong0_params [9]
    const float* __restrict__ sp1,     // strong1_params [9]
    float* __restrict__ out)
{
    // shared: W[a][s] for a=0..3 at sh[a*16+s]; psi0[s] at sh[64+s]
    __shared__ C2 sh[80];

    const int tid = threadIdx.x;

    // ---- issue all parameter loads up front (independent -> MLP)
    const float4 ii  = *(const float4*)inits;
    const float4 e01 = *(const float4*)(inp);        // inp[0..3]
    const float2 n0a = *(const float2*)(inp + 18);   // vert[1]
    const float2 n1a = *(const float2*)(inp + 20);   // vert[2] (measured wire)
    const float4 p0a = *(const float4*)(sp0);
    const float4 p0b = *(const float4*)(sp0 + 4);
    const float  p0c = __ldg(sp0 + 8);
    const float4 p1a = *(const float4*)(sp1);
    const float4 p1b = *(const float4*)(sp1 + 4);
    const float  p1c = __ldg(sp1 + 8);

    Gates G;
    G.ci0 = m_rx(ii.x);
    G.ci1 = m_ry(ii.y);
    G.ci2 = m_rz(ii.z);
    G.ci3 = m_ry(ii.w);
    G.A0 = m_fused(p0a.x, p0a.y, p0a.z);
    G.A1 = m_fused(p0a.w, p0b.x, p0b.y);
    G.A2 = m_fused(p0b.z, p0b.w, p0c);
    G.B0 = m_fused(p1a.x, p1a.y, p1a.z);
    G.B1 = m_fused(p1a.w, p1b.x, p1b.y);
    G.B2 = m_fused(p1b.z, p1b.w, p1c);

    // single-qubit product vectors: v = Rz(phi) Ry(theta) |0>
    auto mkvec = [](float th, float ph, C2* v){
        float ct, st, cp, sp;
        __sincosf(0.5f*th, &st, &ct);
        __sincosf(0.5f*ph, &sp, &cp);
        v[0] = { ct*cp, -ct*sp };
        v[1] = { st*cp,  st*sp };
    };
    C2 vE0[2], vN0[2], vE1[2], vN1[2];
    mkvec(e01.x, e01.y, vE0);   // edge 0  (wire 0)
    mkvec(n0a.x, n0a.y, vN0);   // vert[1] (wire 9)
    mkvec(e01.z, e01.w, vE1);   // edge 1  (wire 1)
    mkvec(n1a.x, n1a.y, vN1);   // vert[2] (wire 10, measured)

    // ---- 5 concurrent evolutions:
    //   task 0..3: W_a = U(|vE1,vN1,a>)     (anc bits = a)
    //   task 4   : psi0 = U(|vE0,vN0,0>)
    const int task = (tid < 4) ? tid : 4;
    const int anc  = (task == 4) ? 0 : task;
    C2 st[16];
#pragma unroll
    for (int s = 0; s < 16; s++){
        C2 prod = (task == 4)
            ? cmul(vE0[(s >> 3) & 1], vN0[(s >> 2) & 1])
            : cmul(vE1[(s >> 3) & 1], vN1[(s >> 2) & 1]);
        st[s] = ((s & 3) == anc) ? prod : C2{0.f, 0.f};
    }
    evolve(st, G);

    if (tid < 5){
#pragma unroll
        for (int s = 0; s < 16; s++)
            sh[task*16 + s] = st[s];
    }
    __syncwarp();

    // ---- combine: 64 terms (en in 0..3, s in 0..15), 2 per lane
    float val = 0.f;
#pragma unroll
    for (int k = 0; k < 2; k++){
        const int T  = tid + 32*k;
        const int en = T >> 4;
        const int s  = T & 15;
        C2 amp = {0.f, 0.f};
#pragma unroll
        for (int a = 0; a < 4; a++)
            amp = cmadd(sh[64 + en*4 + a], sh[a*16 + s], amp);
        float p = amp.x*amp.x + amp.y*amp.y;
        val += ((s >> 2) & 1) ? -p : p;
    }

#pragma unroll
    for (int off = 16; off > 0; off >>= 1)
        val += __shfl_xor_sync(FULLMASK, val, off);
    if (tid == 0) out[0] = val;
}

extern "C" void kernel_launch(void* const* d_in, const int* in_sizes, int n_in,
                              void* d_out, int out_size)
{
    const float* inputs_flat = (const float*)d_in[0];
    const float* inits       = (const float*)d_in[1];
    const float* strong0     = (const float*)d_in[2];
    const float* strong1     = (const float*)d_in[3];
    // d_in[4] (update_params) provably does not affect the measured value.
    QMessagePassing_44272522887312_kernel<<<1, 32>>>(
        inputs_flat, inits, strong0, strong1, (float*)d_out);
}

// round 6
// speedup vs baseline: 1.0047x; 1.0047x over previous
#include <cuda_runtime.h>
#include <cuda_bf16.h>

#define FULLMASK 0xffffffffu

// ---------------------------------------------------------------------------
// Analytic reduction (validated R1-R5, rel_err ~1e-5..2e-5):
// Measured observable is Z on wire 10, touched only by its vertex init and
// edge-loop iteration i=1; everything later commutes and drops out.
//   psi0   = U |vE0>|vN0>|0>|0>            (16-dim, iteration-0 gates)
//   W_a    = U (|vE1>|vN1>|a>)             (same U, shared params)
//   answer = sum_{en,s} (+-)_s | sum_a psi0[en*4+a] * W_a[s] |^2
// Index s: E=bit3, Nb=bit2, A1=bit1, A2=bit0.
//
// R6: distribute each 16-amp evolution over 4 lanes (lane bit1=E, bit0=Nb;
// 4 anc amplitudes per lane in registers). Controlled gates -> lane-predicated
// register butterflies; E/Nb gates -> single-shuffle cross butterflies; most
// CNOTs -> register renames. Gate fusion via closed-form SU(2) product.
// Cuts the per-thread serial instruction stream ~3x (the R5-measured limit).
// ---------------------------------------------------------------------------

struct C2 { float x, y; };
__device__ __forceinline__ C2 cmul(C2 a, C2 b){
    return { a.x*b.x - a.y*b.y, a.x*b.y + a.y*b.x };
}
__device__ __forceinline__ C2 cmadd(C2 a, C2 b, C2 acc){ // acc + a*b
    return { fmaf(a.x, b.x, fmaf(-a.y, b.y, acc.x)),
             fmaf(a.x, b.y, fmaf( a.y, b.x, acc.y)) };
}
__device__ __forceinline__ C2 shf2(C2 v, int m){
    C2 r;
    r.x = __shfl_xor_sync(FULLMASK, v.x, m);
    r.y = __shfl_xor_sync(FULLMASK, v.y, m);
    return r;
}

struct M2 { C2 m00, m01, m10, m11; };

__device__ __forceinline__ M2 m_rx(float t){
    float c, s; __sincosf(0.5f*t, &s, &c);
    return { {c,0.f}, {0.f,-s}, {0.f,-s}, {c,0.f} };
}
__device__ __forceinline__ M2 m_ry(float t){
    float c, s; __sincosf(0.5f*t, &s, &c);
    return { {c,0.f}, {-s,0.f}, {s,0.f}, {c,0.f} };
}
__device__ __forceinline__ M2 m_rz(float t){
    float c, s; __sincosf(0.5f*t, &s, &c);
    return { {c,-s}, {0.f,0.f}, {0.f,0.f}, {c,s} };
}
// Closed-form Rx(t2)*Ry(t1)*Rz(t0)   (ref applies Rz, then Ry, then Rx):
//   m00 =  e^{-iz}(cx*cy - i sx*sy)     m01 = -e^{+iz}(cx*sy + i sx*cy)
//   m10 =  e^{-iz}(cx*sy - i sx*cy)     m11 =  e^{+iz}(cx*cy + i sx*sy)
__device__ __forceinline__ M2 m_fused(float t0, float t1, float t2){
    float cz, sz, cy, sy, cx, sx;
    __sincosf(0.5f*t0, &sz, &cz);
    __sincosf(0.5f*t1, &sy, &cy);
    __sincosf(0.5f*t2, &sx, &cx);
    float A = cx*cy, B = sx*sy, Cc = cx*sy, D = sx*cy;
    M2 M;
    M.m00 = cmul({cz,-sz}, {A,-B});
    C2 t  = cmul({cz, sz}, {Cc, D});
    M.m01 = { -t.x, -t.y };
    M.m10 = cmul({cz,-sz}, {Cc,-D});
    M.m11 = cmul({cz, sz}, {A, B});
    return M;
}

__device__ __forceinline__ void bfly(C2& a0, C2& a1, const M2& U){
    C2 t0 = cmadd(U.m01, a1, cmul(U.m00, a0));
    C2 t1 = cmadd(U.m11, a1, cmul(U.m10, a0));
    a0 = t0; a1 = t1;
}
// 1q gate on a LANE qubit (E: lmask=2, Nb: lmask=1); bit = this lane's value.
__device__ __forceinline__ void cross(C2 a[4], const M2& U, int bit, int lmask){
    C2 cs = bit ? U.m11 : U.m00;
    C2 cp = bit ? U.m10 : U.m01;
#pragma unroll
    for (int r = 0; r < 4; r++){
        C2 ap = shf2(a[r], lmask);
        a[r] = cmadd(cp, ap, cmul(cs, a[r]));
    }
}
__device__ __forceinline__ void cswap(C2& a, C2& b){
    C2 t = a; a = b; b = t;
}

struct Gates {
    M2 ci0, ci1, ci2, ci3;     // controlled init rotations
    M2 A0, A1, A2;             // fused strong0 (wires E,Nb,A1)
    M2 B0, B1, B2;             // fused strong1 (wires A1,Nb,A2)
};

// a[r]: amplitudes with anc index r = (A1<<1)|A2; E,Nb are this lane's bits.
__device__ __forceinline__ void evolve(C2 a[4], const Gates& G, int E, int Nb){
    // ctrl(Rx i0): Nb -> A1
    if (Nb){ bfly(a[0], a[2], G.ci0); bfly(a[1], a[3], G.ci0); }
    // ctrl(Ry i1): E -> A1
    if (E) { bfly(a[0], a[2], G.ci1); bfly(a[1], a[3], G.ci1); }
    // ctrl(Rz i2): Nb -> A2   (diagonal)
    if (Nb){
        a[0] = cmul(a[0], G.ci2.m00); a[1] = cmul(a[1], G.ci2.m11);
        a[2] = cmul(a[2], G.ci2.m00); a[3] = cmul(a[3], G.ci2.m11);
    }
    // ctrl(Ry i3): E -> A2
    if (E) { bfly(a[0], a[1], G.ci3); bfly(a[2], a[3], G.ci3); }
    // strong0: fused 1q on E, Nb, A1
    cross(a, G.A0, E, 2);
    cross(a, G.A1, Nb, 1);
    bfly(a[0], a[2], G.A2); bfly(a[1], a[3], G.A2);
    // cnot(E -> Nb): lanes with E=1 take partner-across-Nb
    {
#pragma unroll
        for (int r = 0; r < 4; r++){
            C2 ap = shf2(a[r], 1);
            if (E) a[r] = ap;
        }
    }
    // cnot(Nb -> A1)
    if (Nb){ cswap(a[0], a[2]); cswap(a[1], a[3]); }
    // cnot(A1 -> E): amps with A1=1 swap across E (unconditional pairwise)
    a[2] = shf2(a[2], 2); a[3] = shf2(a[3], 2);
    // strong1: fused 1q on A1, Nb, A2
    bfly(a[0], a[2], G.B0); bfly(a[1], a[3], G.B0);
    cross(a, G.B1, Nb, 1);
    bfly(a[0], a[1], G.B2); bfly(a[2], a[3], G.B2);
    // cnot(A1 -> Nb)
    a[2] = shf2(a[2], 1); a[3] = shf2(a[3], 1);
    // cnot(Nb -> A2)
    if (Nb){ cswap(a[0], a[1]); cswap(a[2], a[3]); }
    // cnot(A2 -> A1): pure register rename
    cswap(a[1], a[3]);
}

__global__ void __launch_bounds__(32, 1)
QMessagePassing_44272522887312_kernel(
    const float* __restrict__ inp,     // inputs_flat [34]
    const float* __restrict__ inits,   // [4]
    const float* __restrict__ sp0,     // strong0_params [9]
    const float* __restrict__ sp1,     // strong1_params [9]
    float* __restrict__ out)
{
    // sh[t*16 + s]: t=0..3 -> W_t, t=4 -> psi0
    __shared__ C2 sh[80];

    const int tid = threadIdx.x;
    const int sub = tid & 3;
    const int E   = (sub >> 1) & 1;    // lane bit1
    const int Nb  = sub & 1;           // lane bit0
    const int task = (tid < 20) ? (tid >> 2) : 4;

    // ---- parameter loads up front (independent -> MLP)
    const float4 ii  = *(const float4*)inits;
    const float4 e01 = *(const float4*)(inp);        // inp[0..3]
    const float2 n0a = *(const float2*)(inp + 18);   // vert[1] (wire 9)
    const float2 n1a = *(const float2*)(inp + 20);   // vert[2] (wire 10)
    const float4 p0a = *(const float4*)(sp0);
    const float4 p0b = *(const float4*)(sp0 + 4);
    const float  p0c = __ldg(sp0 + 8);
    const float4 p1a = *(const float4*)(sp1);
    const float4 p1b = *(const float4*)(sp1 + 4);
    const float  p1c = __ldg(sp1 + 8);

    Gates G;
    G.ci0 = m_rx(ii.x);
    G.ci1 = m_ry(ii.y);
    G.ci2 = m_rz(ii.z);
    G.ci3 = m_ry(ii.w);
    G.A0 = m_fused(p0a.x, p0a.y, p0a.z);
    G.A1 = m_fused(p0a.w, p0b.x, p0b.y);
    G.A2 = m_fused(p0b.z, p0b.w, p0c);
    G.B0 = m_fused(p1a.x, p1a.y, p1a.z);
    G.B1 = m_fused(p1a.w, p1b.x, p1b.y);
    G.B2 = m_fused(p1b.z, p1b.w, p1c);

    // product vectors: v = Rz(phi) Ry(theta) |0>
    auto mkvec = [](float th, float ph, C2* v){
        float ct, st, cp, sp;
        __sincosf(0.5f*th, &st, &ct);
        __sincosf(0.5f*ph, &sp, &cp);
        v[0] = { ct*cp, -ct*sp };
        v[1] = { st*cp,  st*sp };
    };
    C2 vE0[2], vN0[2], vE1[2], vN1[2];
    mkvec(e01.x, e01.y, vE0);   // edge 0
    mkvec(n0a.x, n0a.y, vN0);   // vert[1]
    mkvec(e01.z, e01.w, vE1);   // edge 1
    mkvec(n1a.x, n1a.y, vN1);   // vert[2] (measured)

    // ---- init: tasks 0..3 = W_a (anc = a), task 4 = psi0 (anc = 0)
    C2 a[4];
    const C2 prod = (task == 4)
        ? cmul(vE0[E], vN0[Nb])
        : cmul(vE1[E], vN1[Nb]);
    const int anc = (task == 4) ? 0 : task;
#pragma unroll
    for (int r = 0; r < 4; r++)
        a[r] = (r == anc) ? prod : C2{0.f, 0.f};

    evolve(a, G, E, Nb);

    if (tid < 20){
#pragma unroll
        for (int r = 0; r < 4; r++)
            sh[task*16 + (sub << 2) + r] = a[r];
    }
    __syncwarp();

    // ---- combine: 64 terms (en 0..3, s 0..15), 2 per lane
    float val = 0.f;
#pragma unroll
    for (int k = 0; k < 2; k++){
        const int T  = tid + 32*k;
        const int en = T >> 4;
        const int s  = T & 15;
        C2 amp = {0.f, 0.f};
#pragma unroll
        for (int q = 0; q < 4; q++)
            amp = cmadd(sh[64 + en*4 + q], sh[q*16 + s], amp);
        float p = amp.x*amp.x + amp.y*amp.y;
        val += ((s >> 2) & 1) ? -p : p;
    }

#pragma unroll
    for (int off = 16; off > 0; off >>= 1)
        val += __shfl_xor_sync(FULLMASK, val, off);
    if (tid == 0) out[0] = val;
}

extern "C" void kernel_launch(void* const* d_in, const int* in_sizes, int n_in,
                              void* d_out, int out_size)
{
    const float* inputs_flat = (const float*)d_in[0];
    const float* inits       = (const float*)d_in[1];
    const float* strong0     = (const float*)d_in[2];
    const float* strong1     = (const float*)d_in[3];
    // d_in[4] (update_params) provably does not affect the measured value.
    QMessagePassing_44272522887312_kernel<<<1, 32>>>(
        inputs_flat, inits, strong0, strong1, (float*)d_out);
}